// round 2
// baseline (speedup 1.0000x reference)
#include <cuda_runtime.h>

// Problem constants
#define T_LEN   2048
#define BATCH   64
#define IDIM    128
#define HDIM    128
#define FCDIM   32
#define ODIM    2
#define CHUNKS  32
#define TC      64          // timesteps per chunk (T_LEN / CHUNKS)
#define TB      16          // tt-block held in accumulator registers (reg-pressure safe)
#define NTHREADS 512

// Scratch (allocation-free rule: __device__ globals)
__device__ float g_Ascr[BATCH * CHUNKS * HDIM];   // chunk-local A = prod f
__device__ float g_Bscr[BATCH * CHUNKS * HDIM];   // chunk-local B
__device__ float g_olast[BATCH * HDIM];           // sigmoid(o) at t = T-1

// Packed fp32x2 FMA (Blackwell FFMA2 — 2x fp32 FMA throughput, PTX-only)
__device__ __forceinline__ unsigned long long ffma2(unsigned long long a,
                                                    unsigned long long b,
                                                    unsigned long long c) {
    unsigned long long d;
    asm("fma.rn.f32x2 %0, %1, %2, %3;" : "=l"(d) : "l"(a), "l"(b), "l"(c));
    return d;
}

__device__ __forceinline__ float lo_plus_hi(unsigned long long v) {
    float2 f = *reinterpret_cast<float2*>(&v);
    return f.x + f.y;
}

__device__ __forceinline__ float fast_sigmoid(float x) {
    return 1.0f / (1.0f + __expf(-x));
}

// ---------------------------------------------------------------------------
// Kernel 1: per-(batch, chunk) gate GEMM + chunk-local affine scan reduction.
// grid = (CHUNKS, BATCH), block = 512. Thread (gate, h) = (tid>>7, tid&127).
// Each thread computes preact[gate][t0+tb .. t0+tb+15][h] via a register-tiled
// dot against the shared x tile, writes preacts to smem, then 128 threads do
// the 64-step affine scan reduction (A, B) for this chunk.
// ---------------------------------------------------------------------------
__global__ void __launch_bounds__(NTHREADS, 1)
gates_kernel(const float* __restrict__ x,
             const float* __restrict__ wg, const float* __restrict__ wi,
             const float* __restrict__ wf, const float* __restrict__ wo,
             const float* __restrict__ bg, const float* __restrict__ bi,
             const float* __restrict__ bf, const float* __restrict__ bo)
{
    extern __shared__ float smem[];
    float* xs  = smem;                  // [TC][IDIM]   = 32 KB
    float* gsm = smem + TC * IDIM;      // [4][TC][HDIM] = 128 KB

    const int b   = blockIdx.y;
    const int ch  = blockIdx.x;
    const int tid = threadIdx.x;
    const int t0  = ch * TC;

    // Load x tile (coalesced float4): x[t0+tt, b, :] for tt in [0,TC)
    for (int idx = tid; idx < TC * IDIM / 4; idx += NTHREADS) {
        const int tt = idx >> 5;        // idx / (IDIM/4)
        const int i4 = idx & 31;
        float4 v = *(const float4*)(x + (size_t)(t0 + tt) * (BATCH * IDIM)
                                      + (size_t)b * IDIM + i4 * 4);
        *(float4*)(xs + tt * IDIM + i4 * 4) = v;
    }
    __syncthreads();

    const int gate = tid >> 7;
    const int h    = tid & 127;
    const float* wsel = (gate == 0) ? wg : (gate == 1) ? wi : (gate == 2) ? wf : wo;
    const float* wrow = wsel + ((size_t)b * HDIM + h) * IDIM;

    #pragma unroll 1
    for (int tb = 0; tb < TC; tb += TB) {
        unsigned long long acc[TB];
        #pragma unroll
        for (int j = 0; j < TB; j++) acc[j] = 0ull;

        #pragma unroll 1                 // keep body within L0 I-cache
        for (int k0 = 0; k0 < IDIM; k0 += 8) {
            // 8 weights for this thread's row, packed as 4 x f32x2 (L1-hot)
            ulonglong2 wa = *(const ulonglong2*)(wrow + k0);
            ulonglong2 wb = *(const ulonglong2*)(wrow + k0 + 4);
            #pragma unroll
            for (int j = 0; j < TB; j++) {
                const ulonglong2* xp =
                    (const ulonglong2*)(xs + (tb + j) * IDIM + k0);
                ulonglong2 x0 = xp[0];   // x[k0..k0+3]   (LDS.128, warp-broadcast)
                ulonglong2 x1 = xp[1];   // x[k0+4..k0+7]
                acc[j] = ffma2(wa.x, x0.x, acc[j]);
                acc[j] = ffma2(wa.y, x0.y, acc[j]);
                acc[j] = ffma2(wb.x, x1.x, acc[j]);
                acc[j] = ffma2(wb.y, x1.y, acc[j]);
            }
        }

        #pragma unroll
        for (int j = 0; j < TB; j++)
            gsm[gate * (TC * HDIM) + (tb + j) * HDIM + h] = lo_plus_hi(acc[j]);
    }
    __syncthreads();

    // Chunk-local affine scan: c_out = A*c_in + B, iterated t ascending.
    if (tid < HDIM) {
        const int hh  = tid;
        const float bgv = bg[b * HDIM + hh];
        const float biv = bi[b * HDIM + hh];
        const float bfv = bf[b * HDIM + hh];
        float A = 1.0f, Bc = 0.0f;
        #pragma unroll 4
        for (int tt = 0; tt < TC; tt++) {
            const float gv = tanhf(gsm[0 * (TC * HDIM) + tt * HDIM + hh] + bgv);
            const float iv = fast_sigmoid(gsm[1 * (TC * HDIM) + tt * HDIM + hh] + biv);
            const float fv = fast_sigmoid(gsm[2 * (TC * HDIM) + tt * HDIM + hh] + bfv);
            Bc = fv * Bc + iv * gv;
            A *= fv;
        }
        g_Ascr[(b * CHUNKS + ch) * HDIM + hh] = A;
        g_Bscr[(b * CHUNKS + ch) * HDIM + hh] = Bc;
        if (ch == CHUNKS - 1) {
            const float ov = fast_sigmoid(
                gsm[3 * (TC * HDIM) + (TC - 1) * HDIM + hh] + bo[b * HDIM + hh]);
            g_olast[b * HDIM + hh] = ov;
        }
    }
}

// ---------------------------------------------------------------------------
// Kernel 2: compose the 32 chunk-affines per (b,h), then the classifier head.
// grid = BATCH, block = HDIM. Full unroll -> ptxas front-batches all 64
// independent loads (MLP) before the 32-FMA dependency chain.
// ---------------------------------------------------------------------------
__global__ void final_kernel(const float* __restrict__ fc1w, const float* __restrict__ fc1b,
                             const float* __restrict__ fc2w, const float* __restrict__ fc2b,
                             float* __restrict__ out)
{
    __shared__ float hs[HDIM];
    __shared__ float zs[FCDIM];
    __shared__ float z2[ODIM];

    const int b = blockIdx.x;
    const int h = threadIdx.x;

    float As[CHUNKS], Bs[CHUNKS];
    #pragma unroll
    for (int ch = 0; ch < CHUNKS; ch++) {
        const int idx = (b * CHUNKS + ch) * HDIM + h;
        As[ch] = g_Ascr[idx];
        Bs[ch] = g_Bscr[idx];
    }
    float c = 0.0f;
    #pragma unroll
    for (int ch = 0; ch < CHUNKS; ch++) c = As[ch] * c + Bs[ch];

    hs[h] = g_olast[b * HDIM + h] * tanhf(c);
    __syncthreads();

    if (h < FCDIM) {
        float z = fc1b[h];
        #pragma unroll 8
        for (int k = 0; k < HDIM; k++) z += fc1w[h * HDIM + k] * hs[k];
        zs[h] = tanhf(z);
    }
    __syncthreads();

    if (h < ODIM) {
        float z = fc2b[h];
        #pragma unroll
        for (int k = 0; k < FCDIM; k++) z += fc2w[h * FCDIM + k] * zs[k];
        z2[h] = z;
    }
    __syncthreads();

    if (h == 0) {
        const float m   = fmaxf(z2[0], z2[1]);
        const float lse = m + logf(expf(z2[0] - m) + expf(z2[1] - m));
        out[b * ODIM + 0] = z2[0] - lse;
        out[b * ODIM + 1] = z2[1] - lse;
    }
}

// ---------------------------------------------------------------------------
extern "C" void kernel_launch(void* const* d_in, const int* in_sizes, int n_in,
                              void* d_out, int out_size)
{
    const float* x   = (const float*)d_in[0];
    const float* wg  = (const float*)d_in[1];
    const float* wi  = (const float*)d_in[2];
    const float* wf  = (const float*)d_in[3];
    const float* wo  = (const float*)d_in[4];
    // d_in[5..8] = w_hg/w_hi/w_hf/w_ho: multiply a zero hidden state -> unused.
    const float* bg  = (const float*)d_in[9];
    const float* bi  = (const float*)d_in[10];
    const float* bf  = (const float*)d_in[11];
    const float* bo  = (const float*)d_in[12];
    const float* f1w = (const float*)d_in[13];
    const float* f1b = (const float*)d_in[14];
    const float* f2w = (const float*)d_in[15];
    const float* f2b = (const float*)d_in[16];

    const int smem_bytes = (TC * IDIM + 4 * TC * HDIM) * (int)sizeof(float); // 160 KB
    cudaFuncSetAttribute(gates_kernel,
                         cudaFuncAttributeMaxDynamicSharedMemorySize, smem_bytes);

    gates_kernel<<<dim3(CHUNKS, BATCH), NTHREADS, smem_bytes>>>(
        x, wg, wi, wf, wo, bg, bi, bf, bo);
    final_kernel<<<BATCH, HDIM>>>(f1w, f1b, f2w, f2b, (float*)d_out);
}

// round 4
// speedup vs baseline: 6.9742x; 6.9742x over previous
#include <cuda_runtime.h>
#include <cuda_bf16.h>
#include <cstdint>

// ---------------- problem constants ----------------
#define T_LEN   2048
#define BATCH   64
#define IDIM    128
#define HDIM    128
#define FCDIM   32
#define ODIM    2
#define TCH     64                  // timesteps per chunk (MMA N)
#define CHUNKS  (T_LEN / TCH)       // 32
#define NTH     512
#define STRB    272                 // tile row stride in bytes (136 bf16, +16B pad)

// ---------------- global scratch (no allocs allowed) ------------------------
__device__ __align__(16) __nv_bfloat16 g_wHi[BATCH * 3 * HDIM * IDIM];
__device__ __align__(16) __nv_bfloat16 g_wLo[BATCH * 3 * HDIM * IDIM];
__device__ float g_Ascr[BATCH * CHUNKS * HDIM];
__device__ float g_Bscr[BATCH * CHUNKS * HDIM];

// ---------------- SMEM layout (bytes) ----------------------------------------
#define SM_BX_HI 0                          // x tile hi: 64 x 136 bf16 = 17408
#define SM_BX_LO 17408
#define SM_WA_HI 34816                      // W tile hi: 128 x 136 bf16 = 34816
#define SM_WA_LO 69632
#define SM_GSM   104448                     // 3 x 128h x 66t fp32 = 101376
#define SM_SEG   205824                     // segA[4][128] + segB[4][128] = 4096
#define SM_TOTAL 209920

// ---------------- helpers ----------------------------------------------------
__device__ __forceinline__ uint32_t smem_u32(const void* p) {
    uint32_t a;
    asm("{ .reg .u64 t; cvta.to.shared.u64 t, %1; cvt.u32.u64 %0, t; }"
        : "=r"(a) : "l"(p));
    return a;
}

__device__ __forceinline__ void ldsm_x4(uint32_t (&r)[4], uint32_t addr) {
    asm volatile("ldmatrix.sync.aligned.m8n8.x4.shared.b16 {%0,%1,%2,%3}, [%4];"
                 : "=r"(r[0]), "=r"(r[1]), "=r"(r[2]), "=r"(r[3]) : "r"(addr));
}

__device__ __forceinline__ void mma_bf16(float (&d)[4], const uint32_t (&a)[4],
                                         uint32_t b0, uint32_t b1) {
    asm volatile("mma.sync.aligned.m16n8k16.row.col.f32.bf16.bf16.f32 "
                 "{%0,%1,%2,%3}, {%4,%5,%6,%7}, {%8,%9}, {%0,%1,%2,%3};"
                 : "+f"(d[0]), "+f"(d[1]), "+f"(d[2]), "+f"(d[3])
                 : "r"(a[0]), "r"(a[1]), "r"(a[2]), "r"(a[3]), "r"(b0), "r"(b1));
}

__device__ __forceinline__ void cvt8(float4 a, float4 bv, uint4& hi, uint4& lo) {
    float f[8] = {a.x, a.y, a.z, a.w, bv.x, bv.y, bv.z, bv.w};
    uint32_t hs[8], ls[8];
    #pragma unroll
    for (int k = 0; k < 8; k++) {
        __nv_bfloat16 h = __float2bfloat16(f[k]);
        __nv_bfloat16 l = __float2bfloat16(f[k] - __bfloat162float(h));
        hs[k] = (uint32_t)__bfloat16_as_ushort(h);
        ls[k] = (uint32_t)__bfloat16_as_ushort(l);
    }
    hi = make_uint4(hs[0] | (hs[1] << 16), hs[2] | (hs[3] << 16),
                    hs[4] | (hs[5] << 16), hs[6] | (hs[7] << 16));
    lo = make_uint4(ls[0] | (ls[1] << 16), ls[2] | (ls[3] << 16),
                    ls[4] | (ls[5] << 16), ls[6] | (ls[7] << 16));
}

__device__ __forceinline__ float fsig(float x)  { return 1.0f / (1.0f + __expf(-x)); }
__device__ __forceinline__ float ftanh(float x) { return 2.0f * fsig(2.0f * x) - 1.0f; }

// ---------------------------------------------------------------------------
// prep_kernel: split W (g,i,f gates) fp32 -> bf16 hi/lo, laid out per (b,gate)
// plane row-major [128h][128i]. grid = 192 (b*3+g), block = 256.
// ---------------------------------------------------------------------------
__global__ void prep_kernel(const float* __restrict__ wg,
                            const float* __restrict__ wi,
                            const float* __restrict__ wf)
{
    const int plane = blockIdx.x;          // b*3 + g
    const int b = plane / 3, g = plane % 3;
    const float* src = ((g == 0) ? wg : (g == 1) ? wi : wf) + (size_t)b * HDIM * IDIM;
    __nv_bfloat16* dh = g_wHi + (size_t)plane * HDIM * IDIM;
    __nv_bfloat16* dl = g_wLo + (size_t)plane * HDIM * IDIM;
    for (int idx = threadIdx.x; idx < HDIM * IDIM; idx += 256) {
        const float v = src[idx];
        const __nv_bfloat16 h = __float2bfloat16(v);
        dh[idx] = h;
        dl[idx] = __float2bfloat16(v - __bfloat162float(h));
    }
}

// ---------------------------------------------------------------------------
// gates_kernel: grid (CHUNKS, BATCH) = (32, 64); block 512 (16 warps).
// Per CTA: preact[h, t] = sum_i W[b,h,i] x[t0+t,b,i] for gates {g,i,f} via
// mma.sync bf16 hi/lo 3-split, staged fp32 in smem, then 4-segment affine scan.
// ---------------------------------------------------------------------------
__global__ void __launch_bounds__(NTH, 1)
gates_kernel(const float* __restrict__ x,
             const float* __restrict__ bg, const float* __restrict__ bi,
             const float* __restrict__ bf_)
{
    extern __shared__ char smem[];
    const uint32_t sb = smem_u32(smem);
    const int tid  = threadIdx.x;
    const int wid  = tid >> 5;
    const int lane = tid & 31;
    const int b  = blockIdx.y;
    const int ch = blockIdx.x;
    const int t0 = ch * TCH;

    // ---- convert x chunk -> bf16 hi/lo tiles (row = t, col = i) ----
    #pragma unroll 2
    for (int u = tid; u < TCH * (IDIM / 8); u += NTH) {   // 1024 units
        const int row = u >> 4, i0 = (u & 15) << 3;
        const float4* p = (const float4*)(x + (size_t)(t0 + row) * (BATCH * IDIM)
                                            + (size_t)b * IDIM + i0);
        uint4 hi, lo; cvt8(p[0], p[1], hi, lo);
        *(uint4*)(smem + SM_BX_HI + row * STRB + i0 * 2) = hi;
        *(uint4*)(smem + SM_BX_LO + row * STRB + i0 * 2) = lo;
    }

    const int wm = wid >> 2, wn = wid & 3;     // 4 x 4 warp grid
    const int m0 = wm * 32, n0 = wn * 16;

    // per-kstep fixed in-warp address components
    const uint32_t a_off = (uint32_t)((m0 + (lane & 15)) * STRB + ((lane >> 4) << 3) * 2);
    const uint32_t b_off = (uint32_t)((n0 + (lane & 7) + ((lane >> 4) << 3)) * STRB
                                      + (((lane >> 3) & 1) << 3) * 2);

    for (int g = 0; g < 3; g++) {
        if (g > 0) __syncthreads();    // previous gate's ldsm done before W overwrite
        // ---- load pre-split W tiles into padded smem ----
        const __nv_bfloat16* sh = g_wHi + (size_t)(b * 3 + g) * (HDIM * IDIM);
        const __nv_bfloat16* sl = g_wLo + (size_t)(b * 3 + g) * (HDIM * IDIM);
        #pragma unroll 4
        for (int u = tid; u < HDIM * (IDIM / 8); u += NTH) {   // 2048 units
            const int row = u >> 4, i0 = (u & 15) << 3;
            *(uint4*)(smem + SM_WA_HI + row * STRB + i0 * 2) =
                *(const uint4*)(sh + row * IDIM + i0);
            *(uint4*)(smem + SM_WA_LO + row * STRB + i0 * 2) =
                *(const uint4*)(sl + row * IDIM + i0);
        }
        __syncthreads();

        // ---- K loop: 24 k-steps = 3 splits x 8 (hi*hi, hi*lo, lo*hi) ----
        float d[2][2][4];
        #pragma unroll
        for (int mi = 0; mi < 2; mi++)
            #pragma unroll
            for (int ni = 0; ni < 2; ni++)
                #pragma unroll
                for (int r = 0; r < 4; r++) d[mi][ni][r] = 0.0f;

        #pragma unroll
        for (int kk = 0; kk < 24; kk++) {
            const uint32_t apl = (kk < 16) ? SM_WA_HI : SM_WA_LO;
            const uint32_t bpl = (kk >= 8 && kk < 16) ? SM_BX_LO : SM_BX_HI;
            const uint32_t kb  = (uint32_t)((kk & 7) << 5);   // k0*2 bytes (k0=16*(kk&7))
            uint32_t a0[4], a1[4], bb[4];
            ldsm_x4(a0, sb + apl + a_off + kb);
            ldsm_x4(a1, sb + apl + a_off + kb + 16 * STRB);
            ldsm_x4(bb, sb + bpl + b_off + kb);
            mma_bf16(d[0][0], a0, bb[0], bb[1]);
            mma_bf16(d[0][1], a0, bb[2], bb[3]);
            mma_bf16(d[1][0], a1, bb[0], bb[1]);
            mma_bf16(d[1][1], a1, bb[2], bb[3]);
        }

        // ---- stage preacts to gsm[g][h][66] ----
        float* gp = (float*)(smem + SM_GSM) + g * (HDIM * 66);
        #pragma unroll
        for (int mi = 0; mi < 2; mi++) {
            #pragma unroll
            for (int ni = 0; ni < 2; ni++) {
                const int h  = m0 + mi * 16 + (lane >> 2);
                const int tt = n0 + ni * 8 + ((lane & 3) << 1);
                *(float2*)(gp + h * 66 + tt)       = make_float2(d[mi][ni][0], d[mi][ni][1]);
                *(float2*)(gp + (h + 8) * 66 + tt) = make_float2(d[mi][ni][2], d[mi][ni][3]);
            }
        }
    }
    __syncthreads();

    // ---- 4-segment affine scan: warp = (hw, seg); h = hw*32+lane ----
    const int seg = wid & 3, hw = wid >> 2;
    const int h   = hw * 32 + lane;
    const float* g0 = (const float*)(smem + SM_GSM) + 0 * (HDIM * 66) + h * 66;
    const float* g1 = (const float*)(smem + SM_GSM) + 1 * (HDIM * 66) + h * 66;
    const float* g2 = (const float*)(smem + SM_GSM) + 2 * (HDIM * 66) + h * 66;
    const float bgv = bg[b * HDIM + h];
    const float biv = bi[b * HDIM + h];
    const float bfv = bf_[b * HDIM + h];

    float A = 1.0f, B = 0.0f;
    #pragma unroll 4
    for (int tt = seg * 16; tt < seg * 16 + 16; tt++) {
        const float gv = ftanh(g0[tt] + bgv);
        const float iv = fsig (g1[tt] + biv);
        const float fv = fsig (g2[tt] + bfv);
        B = fv * B + iv * gv;
        A *= fv;
    }
    float* segA = (float*)(smem + SM_SEG);
    float* segB = segA + 512;
    segA[seg * 128 + h] = A;
    segB[seg * 128 + h] = B;
    __syncthreads();

    if (seg == 0) {
        float At = segA[h], Bt = segB[h];
        #pragma unroll
        for (int s = 1; s < 4; s++) {
            const float As = segA[s * 128 + h], Bs = segB[s * 128 + h];
            Bt = As * Bt + Bs;
            At = As * At;
        }
        g_Ascr[(b * CHUNKS + ch) * HDIM + h] = At;
        g_Bscr[(b * CHUNKS + ch) * HDIM + h] = Bt;
    }
}

// ---------------------------------------------------------------------------
// final_kernel: o-gate at t = T-1 (direct dot), compose 32 chunk-affines,
// classifier head. grid = BATCH, block = HDIM.
// ---------------------------------------------------------------------------
__global__ void final_kernel(const float* __restrict__ x,
                             const float* __restrict__ wo, const float* __restrict__ bo,
                             const float* __restrict__ fc1w, const float* __restrict__ fc1b,
                             const float* __restrict__ fc2w, const float* __restrict__ fc2b,
                             float* __restrict__ out)
{
    __shared__ float xrow[IDIM];
    __shared__ float hs[HDIM];
    __shared__ float zs[FCDIM];
    __shared__ float z2[ODIM];

    const int b = blockIdx.x;
    const int h = threadIdx.x;

    xrow[h] = x[(size_t)(T_LEN - 1) * (BATCH * IDIM) + b * IDIM + h];
    __syncthreads();

    // o-gate pre-activation (recurrent term is zero)
    float opre = bo[b * HDIM + h];
    const float* wr = wo + ((size_t)b * HDIM + h) * IDIM;
    #pragma unroll 8
    for (int k = 0; k < IDIM; k++) opre += wr[k] * xrow[k];
    const float o = 1.0f / (1.0f + expf(-opre));

    // compose chunk affines (fully unrolled -> front-batched loads)
    float As[CHUNKS], Bs[CHUNKS];
    #pragma unroll
    for (int ch = 0; ch < CHUNKS; ch++) {
        const int idx = (b * CHUNKS + ch) * HDIM + h;
        As[ch] = g_Ascr[idx];
        Bs[ch] = g_Bscr[idx];
    }
    float c = 0.0f;
    #pragma unroll
    for (int ch = 0; ch < CHUNKS; ch++) c = As[ch] * c + Bs[ch];

    hs[h] = o * tanhf(c);
    __syncthreads();

    if (h < FCDIM) {
        float z = fc1b[h];
        #pragma unroll 8
        for (int k = 0; k < HDIM; k++) z += fc1w[h * HDIM + k] * hs[k];
        zs[h] = tanhf(z);
    }
    __syncthreads();

    if (h < ODIM) {
        float z = fc2b[h];
        #pragma unroll
        for (int k = 0; k < FCDIM; k++) z += fc2w[h * FCDIM + k] * zs[k];
        z2[h] = z;
    }
    __syncthreads();

    if (h == 0) {
        const float m   = fmaxf(z2[0], z2[1]);
        const float lse = m + logf(expf(z2[0] - m) + expf(z2[1] - m));
        out[b * ODIM + 0] = z2[0] - lse;
        out[b * ODIM + 1] = z2[1] - lse;
    }
}

// ---------------------------------------------------------------------------
extern "C" void kernel_launch(void* const* d_in, const int* in_sizes, int n_in,
                              void* d_out, int out_size)
{
    const float* x   = (const float*)d_in[0];
    const float* wg  = (const float*)d_in[1];
    const float* wi  = (const float*)d_in[2];
    const float* wf  = (const float*)d_in[3];
    const float* wo  = (const float*)d_in[4];
    // d_in[5..8] (recurrent weights) multiply a zero hidden state -> unused.
    const float* bg  = (const float*)d_in[9];
    const float* bi  = (const float*)d_in[10];
    const float* bf  = (const float*)d_in[11];
    const float* bo  = (const float*)d_in[12];
    const float* f1w = (const float*)d_in[13];
    const float* f1b = (const float*)d_in[14];
    const float* f2w = (const float*)d_in[15];
    const float* f2b = (const float*)d_in[16];

    cudaFuncSetAttribute(gates_kernel,
                         cudaFuncAttributeMaxDynamicSharedMemorySize, SM_TOTAL);

    prep_kernel<<<BATCH * 3, 256>>>(wg, wi, wf);
    gates_kernel<<<dim3(CHUNKS, BATCH), NTH, SM_TOTAL>>>(x, bg, bi, bf);
    final_kernel<<<BATCH, HDIM>>>(x, wo, bo, f1w, f1b, f2w, f2b, (float*)d_out);
}

// round 5
// speedup vs baseline: 10.5158x; 1.5078x over previous
#include <cuda_runtime.h>
#include <cuda_fp16.h>
#include <cstdint>

// ---------------- problem constants ----------------
#define T_LEN   2048
#define BATCH   64
#define IDIM    128
#define HDIM    128
#define FCDIM   32
#define ODIM    2
#define TCH     64                  // timesteps per chunk (MMA N)
#define CHUNKS  (T_LEN / TCH)       // 32
#define NTH     512
#define STRB    272                 // tile row stride bytes (128 fp16 = 256B + 16B pad)

// ---------------- global scratch -------------------------------------------
__device__ float2 g_AB[BATCH * CHUNKS * HDIM];   // chunk affine (A, B) per (b,ch,h)

// ---------------- SMEM layout (bytes) --------------------------------------
#define SM_X     0                           // x tile: 64 x 272B  = 17408
#define SM_W     17408                       // W tiles: 3 x 128 x 272B = 104448
#define SM_SEG   121856                      // seg[h][wn] float2 = 4096
#define SM_TOTAL 125952

// ---------------- helpers ---------------------------------------------------
__device__ __forceinline__ uint32_t smem_u32(const void* p) {
    uint32_t a;
    asm("{ .reg .u64 t; cvta.to.shared.u64 t, %1; cvt.u32.u64 %0, t; }"
        : "=r"(a) : "l"(p));
    return a;
}

__device__ __forceinline__ void ldsm_x4(uint32_t (&r)[4], uint32_t addr) {
    asm volatile("ldmatrix.sync.aligned.m8n8.x4.shared.b16 {%0,%1,%2,%3}, [%4];"
                 : "=r"(r[0]), "=r"(r[1]), "=r"(r[2]), "=r"(r[3]) : "r"(addr));
}

__device__ __forceinline__ void mma_f16(float (&d)[4], const uint32_t (&a)[4],
                                        uint32_t b0, uint32_t b1) {
    asm volatile("mma.sync.aligned.m16n8k16.row.col.f32.f16.f16.f32 "
                 "{%0,%1,%2,%3}, {%4,%5,%6,%7}, {%8,%9}, {%0,%1,%2,%3};"
                 : "+f"(d[0]), "+f"(d[1]), "+f"(d[2]), "+f"(d[3])
                 : "r"(a[0]), "r"(a[1]), "r"(a[2]), "r"(a[3]), "r"(b0), "r"(b1));
}

// pack 8 fp32 -> 8 fp16 in a uint4
__device__ __forceinline__ uint4 cvt8h(float4 a, float4 b) {
    uint4 r;
    r.x = __half_as_ushort(__float2half_rn(a.x)) |
          ((uint32_t)__half_as_ushort(__float2half_rn(a.y)) << 16);
    r.y = __half_as_ushort(__float2half_rn(a.z)) |
          ((uint32_t)__half_as_ushort(__float2half_rn(a.w)) << 16);
    r.z = __half_as_ushort(__float2half_rn(b.x)) |
          ((uint32_t)__half_as_ushort(__float2half_rn(b.y)) << 16);
    r.w = __half_as_ushort(__float2half_rn(b.z)) |
          ((uint32_t)__half_as_ushort(__float2half_rn(b.w)) << 16);
    return r;
}

__device__ __forceinline__ float fsig(float x)  { return 1.0f / (1.0f + __expf(-x)); }
__device__ __forceinline__ float ftanh(float x) { return 2.0f * fsig(2.0f * x) - 1.0f; }

// 8 k-steps of m32n16 fp16 MMA against the shared x tile
__device__ __forceinline__ void gate_mma(uint32_t sb, uint32_t wbase,
                                         uint32_t a_off, uint32_t b_off,
                                         float (&d)[2][2][4]) {
    #pragma unroll
    for (int mi = 0; mi < 2; mi++)
        #pragma unroll
        for (int ni = 0; ni < 2; ni++)
            #pragma unroll
            for (int r = 0; r < 4; r++) d[mi][ni][r] = 0.0f;
    #pragma unroll
    for (int kk = 0; kk < 8; kk++) {
        const uint32_t kb = (uint32_t)kk << 5;   // 16 fp16 = 32 bytes
        uint32_t a0[4], a1[4], bb[4];
        ldsm_x4(a0, sb + wbase + a_off + kb);
        ldsm_x4(a1, sb + wbase + a_off + kb + 16 * STRB);
        ldsm_x4(bb, sb + SM_X + b_off + kb);
        mma_f16(d[0][0], a0, bb[0], bb[1]);
        mma_f16(d[0][1], a0, bb[2], bb[3]);
        mma_f16(d[1][0], a1, bb[0], bb[1]);
        mma_f16(d[1][1], a1, bb[2], bb[3]);
    }
}

// ---------------------------------------------------------------------------
// gates_kernel: grid (CHUNKS, BATCH) = (32, 64); block 512 (16 warps, 4m x 4n).
// preact[h,t] = sum_i W[b,h,i] x[t0+t,b,i] for gates {g,i,f} via single-pass
// fp16 mma.sync; activations + chunk affine scan fully in registers
// (pair -> quad-shuffle -> ni -> cross-warp segments).
// ---------------------------------------------------------------------------
__global__ void __launch_bounds__(NTH, 1)
gates_kernel(const float* __restrict__ x,
             const float* __restrict__ wg, const float* __restrict__ wi,
             const float* __restrict__ wf,
             const float* __restrict__ bg, const float* __restrict__ bi,
             const float* __restrict__ bf_)
{
    extern __shared__ char smem[];
    const uint32_t sb = smem_u32(smem);
    const int tid  = threadIdx.x;
    const int wid  = tid >> 5;
    const int lane = tid & 31;
    const int b  = blockIdx.y;
    const int ch = blockIdx.x;
    const int t0 = ch * TCH;

    // ---- convert x chunk -> fp16 tile (row = t, col = i) ----
    #pragma unroll 2
    for (int u = tid; u < TCH * (IDIM / 8); u += NTH) {      // 1024 units
        const int row = u >> 4, i0 = (u & 15) << 3;
        const float4* p = (const float4*)(x + (size_t)(t0 + row) * (BATCH * IDIM)
                                            + (size_t)b * IDIM + i0);
        *(uint4*)(smem + SM_X + row * STRB + i0 * 2) = cvt8h(p[0], p[1]);
    }

    // ---- load + convert all 3 gate W tiles (fp32 gmem -> fp16 smem) ----
    const float* wsel[3] = {wg, wi, wf};
    #pragma unroll 4
    for (int u = tid; u < 3 * HDIM * (IDIM / 8); u += NTH) { // 6144 units
        const int g = u >> 11, rem = u & 2047;
        const int row = rem >> 4, i0 = (rem & 15) << 3;
        const float4* p = (const float4*)(wsel[g] + ((size_t)b * HDIM + row) * IDIM + i0);
        *(uint4*)(smem + SM_W + g * (HDIM * STRB) + row * STRB + i0 * 2) =
            cvt8h(p[0], p[1]);
    }
    __syncthreads();

    const int wm = wid >> 2, wn = wid & 3;      // 4 x 4 warp grid
    const int m0 = wm * 32, n0 = wn * 16;
    const int j  = lane & 3;                    // t-pair index within quad
    const int r  = lane >> 2;                   // row-within-8

    const uint32_t a_off = (uint32_t)((m0 + (lane & 15)) * STRB + ((lane >> 4) << 3) * 2);
    const uint32_t b_off = (uint32_t)((n0 + (lane & 7) + ((lane >> 4) << 3)) * STRB
                                      + (((lane >> 3) & 1) << 3) * 2);

    // biases for this thread's 4 h-rows: [mi][hi]
    float bgv[2][2], biv[2][2], bfv[2][2];
    #pragma unroll
    for (int mi = 0; mi < 2; mi++)
        #pragma unroll
        for (int hi = 0; hi < 2; hi++) {
            const int h = m0 + 16 * mi + 8 * hi + r;
            bgv[mi][hi] = bg[b * HDIM + h];
            biv[mi][hi] = bi[b * HDIM + h];
            bfv[mi][hi] = bf_[b * HDIM + h];
        }

    float d[2][2][4];
    float G[2][2][4], E[2][2][4], F[2][2][4];

    // gate g (tanh)
    gate_mma(sb, SM_W + 0 * (HDIM * STRB), a_off, b_off, d);
    #pragma unroll
    for (int mi = 0; mi < 2; mi++)
        #pragma unroll
        for (int ni = 0; ni < 2; ni++)
            #pragma unroll
            for (int k = 0; k < 4; k++)
                G[mi][ni][k] = ftanh(d[mi][ni][k] + bgv[mi][k >> 1]);

    // gate i (sigmoid) -> E = i * g
    gate_mma(sb, SM_W + 1 * (HDIM * STRB), a_off, b_off, d);
    #pragma unroll
    for (int mi = 0; mi < 2; mi++)
        #pragma unroll
        for (int ni = 0; ni < 2; ni++)
            #pragma unroll
            for (int k = 0; k < 4; k++)
                E[mi][ni][k] = fsig(d[mi][ni][k] + biv[mi][k >> 1]) * G[mi][ni][k];

    // gate f (sigmoid)
    gate_mma(sb, SM_W + 2 * (HDIM * STRB), a_off, b_off, d);
    #pragma unroll
    for (int mi = 0; mi < 2; mi++)
        #pragma unroll
        for (int ni = 0; ni < 2; ni++)
            #pragma unroll
            for (int k = 0; k < 4; k++)
                F[mi][ni][k] = fsig(d[mi][ni][k] + bfv[mi][k >> 1]);

    // ---- in-register affine scan ----
    // pair compose (t = even then odd): A = F1*F0, B = F1*E0 + E1
    float A[2][2][2], Bv[2][2][2];   // [mi][hi][ni]
    #pragma unroll
    for (int mi = 0; mi < 2; mi++)
        #pragma unroll
        for (int hi = 0; hi < 2; hi++)
            #pragma unroll
            for (int ni = 0; ni < 2; ni++) {
                const float e0 = E[mi][ni][2 * hi], e1 = E[mi][ni][2 * hi + 1];
                const float f0 = F[mi][ni][2 * hi], f1 = F[mi][ni][2 * hi + 1];
                A[mi][hi][ni]  = f1 * f0;
                Bv[mi][hi][ni] = f1 * e0 + e1;
            }
    // quad scan over j (segmented width-4 inclusive affine scan, j=0 first)
    #pragma unroll
    for (int delta = 1; delta <= 2; delta <<= 1) {
        #pragma unroll
        for (int mi = 0; mi < 2; mi++)
            #pragma unroll
            for (int hi = 0; hi < 2; hi++)
                #pragma unroll
                for (int ni = 0; ni < 2; ni++) {
                    const float pA = __shfl_up_sync(0xffffffffu, A[mi][hi][ni],  delta, 4);
                    const float pB = __shfl_up_sync(0xffffffffu, Bv[mi][hi][ni], delta, 4);
                    if (j >= delta) {
                        Bv[mi][hi][ni] = A[mi][hi][ni] * pB + Bv[mi][hi][ni];
                        A[mi][hi][ni]  = A[mi][hi][ni] * pA;
                    }
                }
    }
    // ni compose (ni=0 first) and stage per-warp segment
    float2* seg = (float2*)(smem + SM_SEG);      // [HDIM][4 n-warps]
    if (j == 3) {
        #pragma unroll
        for (int mi = 0; mi < 2; mi++)
            #pragma unroll
            for (int hi = 0; hi < 2; hi++) {
                const float At = A[mi][hi][1] * A[mi][hi][0];
                const float Bt = A[mi][hi][1] * Bv[mi][hi][0] + Bv[mi][hi][1];
                const int h = m0 + 16 * mi + 8 * hi + r;
                seg[h * 4 + wn] = make_float2(At, Bt);
            }
    }
    __syncthreads();

    // cross-warp compose (wn ascending) and write chunk affine
    if (tid < HDIM) {
        const int h = tid;
        float2 s0 = seg[h * 4 + 0];
        float At = s0.x, Bt = s0.y;
        #pragma unroll
        for (int s = 1; s < 4; s++) {
            const float2 ss = seg[h * 4 + s];
            Bt = ss.x * Bt + ss.y;
            At = ss.x * At;
        }
        g_AB[(b * CHUNKS + ch) * HDIM + h] = make_float2(At, Bt);
    }
}

// ---------------------------------------------------------------------------
// final_kernel: o-gate at t = T-1 (direct fp32 dot), compose 32 chunk
// affines, classifier head. grid = BATCH, block = HDIM.
// ---------------------------------------------------------------------------
__global__ void final_kernel(const float* __restrict__ x,
                             const float* __restrict__ wo, const float* __restrict__ bo,
                             const float* __restrict__ fc1w, const float* __restrict__ fc1b,
                             const float* __restrict__ fc2w, const float* __restrict__ fc2b,
                             float* __restrict__ out)
{
    __shared__ float4 xrow[IDIM / 4];
    __shared__ float  hs[HDIM];
    __shared__ float  zs[FCDIM];
    __shared__ float  z2[ODIM];

    const int b = blockIdx.x;
    const int h = threadIdx.x;

    if (h < IDIM / 4)
        xrow[h] = ((const float4*)(x + (size_t)(T_LEN - 1) * (BATCH * IDIM) + b * IDIM))[h];

    // front-batched chunk-affine loads
    float2 AB[CHUNKS];
    #pragma unroll
    for (int ch = 0; ch < CHUNKS; ch++)
        AB[ch] = g_AB[(b * CHUNKS + ch) * HDIM + h];
    __syncthreads();

    // o-gate pre-activation (recurrent term is zero)
    float opre = bo[b * HDIM + h];
    const float4* wr = (const float4*)(wo + ((size_t)b * HDIM + h) * IDIM);
    #pragma unroll 8
    for (int k = 0; k < IDIM / 4; k++) {
        const float4 w4 = wr[k], x4 = xrow[k];
        opre += w4.x * x4.x + w4.y * x4.y + w4.z * x4.z + w4.w * x4.w;
    }
    const float o = 1.0f / (1.0f + expf(-opre));

    float c = 0.0f;
    #pragma unroll
    for (int ch = 0; ch < CHUNKS; ch++) c = AB[ch].x * c + AB[ch].y;

    hs[h] = o * tanhf(c);
    __syncthreads();

    if (h < FCDIM) {
        float z = fc1b[h];
        const float4* w4p = (const float4*)(fc1w + h * HDIM);
        #pragma unroll 8
        for (int k = 0; k < HDIM / 4; k++) {
            const float4 w4 = w4p[k];
            z += w4.x * hs[4 * k] + w4.y * hs[4 * k + 1]
               + w4.z * hs[4 * k + 2] + w4.w * hs[4 * k + 3];
        }
        zs[h] = tanhf(z);
    }
    __syncthreads();

    if (h < ODIM) {
        float z = fc2b[h];
        #pragma unroll
        for (int k = 0; k < FCDIM; k++) z += fc2w[h * FCDIM + k] * zs[k];
        z2[h] = z;
    }
    __syncthreads();

    if (h == 0) {
        const float m   = fmaxf(z2[0], z2[1]);
        const float lse = m + logf(expf(z2[0] - m) + expf(z2[1] - m));
        out[b * ODIM + 0] = z2[0] - lse;
        out[b * ODIM + 1] = z2[1] - lse;
    }
}

// ---------------------------------------------------------------------------
extern "C" void kernel_launch(void* const* d_in, const int* in_sizes, int n_in,
                              void* d_out, int out_size)
{
    const float* x   = (const float*)d_in[0];
    const float* wg  = (const float*)d_in[1];
    const float* wi  = (const float*)d_in[2];
    const float* wf  = (const float*)d_in[3];
    const float* wo  = (const float*)d_in[4];
    // d_in[5..8] (recurrent weights) multiply a zero hidden state -> unused.
    const float* bg  = (const float*)d_in[9];
    const float* bi  = (const float*)d_in[10];
    const float* bf  = (const float*)d_in[11];
    const float* bo  = (const float*)d_in[12];
    const float* f1w = (const float*)d_in[13];
    const float* f1b = (const float*)d_in[14];
    const float* f2w = (const float*)d_in[15];
    const float* f2b = (const float*)d_in[16];

    cudaFuncSetAttribute(gates_kernel,
                         cudaFuncAttributeMaxDynamicSharedMemorySize, SM_TOTAL);

    gates_kernel<<<dim3(CHUNKS, BATCH), NTH, SM_TOTAL>>>(x, wg, wi, wf, bg, bi, bf);
    final_kernel<<<BATCH, HDIM>>>(x, wo, bo, f1w, f1b, f2w, f2b, (float*)d_out);
}

// round 8
// speedup vs baseline: 16.1479x; 1.5356x over previous
#include <cuda_runtime.h>
#include <cuda_fp16.h>
#include <cstdint>

// ---------------- problem constants ----------------
#define T_LEN   2048
#define BATCH   64
#define IDIM    128
#define HDIM    128
#define FCDIM   32
#define ODIM    2
#define TCH     32                  // timesteps per chunk (MMA N)
#define CHUNKS  (T_LEN / TCH)       // 64
#define NTH     512

// ---------------- global scratch -------------------------------------------
__device__ __align__(16) __half g_wH[3 * BATCH * HDIM * IDIM];  // fp16 W (g,i,f)
__device__ float2 g_AB[BATCH * CHUNKS * HDIM];                  // chunk affine (A,B)

// ---------------- SMEM layout (bytes) --------------------------------------
// x tile 32 x 256B = 8192; W tiles 3 x 128 x 256B = 98304. seg reuses x region.
#define SM_X     0
#define SM_W     8192
#define SM_TOTAL 106496

// ---------------- helpers ---------------------------------------------------
__device__ __forceinline__ uint32_t smem_u32(const void* p) {
    uint32_t a;
    asm("{ .reg .u64 t; cvta.to.shared.u64 t, %1; cvt.u32.u64 %0, t; }"
        : "=r"(a) : "l"(p));
    return a;
}
__device__ __forceinline__ void cp_async16(uint32_t dst, const void* src) {
    asm volatile("cp.async.cg.shared.global [%0], [%1], 16;"
                 :: "r"(dst), "l"(src) : "memory");
}
__device__ __forceinline__ void cp_commit_wait() {
    asm volatile("cp.async.commit_group;" ::: "memory");
    asm volatile("cp.async.wait_group 0;" ::: "memory");
}
__device__ __forceinline__ void ldsm_x4(uint32_t (&r)[4], uint32_t addr) {
    asm volatile("ldmatrix.sync.aligned.m8n8.x4.shared.b16 {%0,%1,%2,%3}, [%4];"
                 : "=r"(r[0]), "=r"(r[1]), "=r"(r[2]), "=r"(r[3]) : "r"(addr));
}
__device__ __forceinline__ void ldsm_x2(uint32_t (&r)[2], uint32_t addr) {
    asm volatile("ldmatrix.sync.aligned.m8n8.x2.shared.b16 {%0,%1}, [%2];"
                 : "=r"(r[0]), "=r"(r[1]) : "r"(addr));
}
__device__ __forceinline__ void mma_f16(float (&d)[4], const uint32_t (&a)[4],
                                        uint32_t b0, uint32_t b1) {
    asm volatile("mma.sync.aligned.m16n8k16.row.col.f32.f16.f16.f32 "
                 "{%0,%1,%2,%3}, {%4,%5,%6,%7}, {%8,%9}, {%0,%1,%2,%3};"
                 : "+f"(d[0]), "+f"(d[1]), "+f"(d[2]), "+f"(d[3])
                 : "r"(a[0]), "r"(a[1]), "r"(a[2]), "r"(a[3]), "r"(b0), "r"(b1));
}
// pack 8 fp32 -> 8 fp16
__device__ __forceinline__ uint4 cvt8h(float4 a, float4 b) {
    uint4 r;
    r.x = __half_as_ushort(__float2half_rn(a.x)) |
          ((uint32_t)__half_as_ushort(__float2half_rn(a.y)) << 16);
    r.y = __half_as_ushort(__float2half_rn(a.z)) |
          ((uint32_t)__half_as_ushort(__float2half_rn(a.w)) << 16);
    r.z = __half_as_ushort(__float2half_rn(b.x)) |
          ((uint32_t)__half_as_ushort(__float2half_rn(b.y)) << 16);
    r.w = __half_as_ushort(__float2half_rn(b.z)) |
          ((uint32_t)__half_as_ushort(__float2half_rn(b.w)) << 16);
    return r;
}
__device__ __forceinline__ float fsig(float x)  { return 1.0f / (1.0f + __expf(-x)); }
__device__ __forceinline__ float ftanh(float x) { return 2.0f * fsig(2.0f * x) - 1.0f; }

// ---------------------------------------------------------------------------
// prep_kernel: W (g,i,f) fp32 -> fp16 global, layout [g][b][h][i] row-major.
// grid = 192 (g*64 + b), block = 256.
// ---------------------------------------------------------------------------
__global__ void prep_kernel(const float* __restrict__ wg,
                            const float* __restrict__ wi,
                            const float* __restrict__ wf)
{
    const int plane = blockIdx.x;
    const int g = plane >> 6, b = plane & 63;
    const float* src = ((g == 0) ? wg : (g == 1) ? wi : wf) + (size_t)b * HDIM * IDIM;
    __half* dst = g_wH + (size_t)plane * HDIM * IDIM;
    #pragma unroll 4
    for (int u = threadIdx.x; u < HDIM * IDIM / 8; u += 256) {
        const float4* p = (const float4*)(src + u * 8);
        *(uint4*)(dst + u * 8) = cvt8h(p[0], p[1]);
    }
}

// ---------------------------------------------------------------------------
// gates_kernel: grid (CHUNKS, BATCH) = (64, 64); block 512, occ 2.
// preact[h,t] = sum_i W[b,h,i] x[t0+t,b,i] for gates {g,i,f} via fp16
// mma.sync; W via cp.async (prepped fp16), XOR-swizzled 256B-row tiles;
// activations + chunk affine scan in registers (pair -> quad shfl -> 4 segs).
// ---------------------------------------------------------------------------
__global__ void __launch_bounds__(NTH, 2)
gates_kernel(const float* __restrict__ x,
             const float* __restrict__ bg, const float* __restrict__ bi,
             const float* __restrict__ bf_)
{
    extern __shared__ char smem[];
    const uint32_t sb = smem_u32(smem);
    const int tid  = threadIdx.x;
    const int wid  = tid >> 5;
    const int lane = tid & 31;
    const int b  = blockIdx.y;
    const int ch = blockIdx.x;
    const int t0 = ch * TCH;

    // ---- cp.async all 3 gate W tiles (fp16, swizzled 256B rows) ----
    #pragma unroll
    for (int it = 0; it < 12; it++) {                 // 6144 16B units
        const int u = tid + it * NTH;
        const int g = u >> 11, rem = u & 2047;
        const int row = rem >> 4, cb = (rem & 15) << 4;       // col bytes
        const __half* src = g_wH + ((size_t)(g * BATCH + b) * (HDIM * IDIM))
                                 + row * IDIM + (cb >> 1);
        cp_async16(sb + SM_W + g * 32768 + row * 256 + (cb ^ ((row & 7) << 4)), src);
    }
    // ---- x chunk: 512 16B units -> fp16 swizzled (overlaps cp.async) ----
    {
        const int row = tid >> 4, cb = (tid & 15) << 4;       // col bytes (fp16)
        // element index = cb/2 halves == cb/2 floats in the fp32 source row
        const float4* p = (const float4*)(x + (size_t)(t0 + row) * (BATCH * IDIM)
                                            + (size_t)b * IDIM + (cb >> 1));
        *(uint4*)(smem + SM_X + row * 256 + (cb ^ ((row & 7) << 4))) = cvt8h(p[0], p[1]);
    }
    cp_commit_wait();
    __syncthreads();

    // ---- warp tiling: 4m x 4n; warp tile m32 x n8 ----
    const int wm = wid >> 2, wn = wid & 3;
    const int m0 = wm * 32, n0 = wn * 8;
    const int j  = lane & 3;                    // t-pair index
    const int r  = lane >> 2;                   // row-within-8

    const uint32_t rxor  = (uint32_t)((lane & 7) << 4);
    const uint32_t a_row = sb + SM_W + (uint32_t)(m0 + (lane & 15)) * 256;
    const uint32_t acl   = (uint32_t)((lane >> 4) << 4);
    const uint32_t b_row = sb + SM_X + (uint32_t)(n0 + (lane & 7)) * 256;
    const uint32_t bcl   = (uint32_t)(((lane >> 3) & 1) << 4);

    float bias[3][2][2];
    #pragma unroll
    for (int mi = 0; mi < 2; mi++)
        #pragma unroll
        for (int hi = 0; hi < 2; hi++) {
            const int h = m0 + 16 * mi + 8 * hi + r;
            bias[0][mi][hi] = bg[b * HDIM + h];
            bias[1][mi][hi] = bi[b * HDIM + h];
            bias[2][mi][hi] = bf_[b * HDIM + h];
        }

    float G[2][4], E[2][4], F[2][4];
    #pragma unroll
    for (int g = 0; g < 3; g++) {
        float d[2][4];
        #pragma unroll
        for (int mi = 0; mi < 2; mi++)
            #pragma unroll
            for (int k = 0; k < 4; k++) d[mi][k] = 0.0f;
        const uint32_t wofs = (uint32_t)g * 32768u;
        #pragma unroll
        for (int kk = 0; kk < 8; kk++) {
            const uint32_t kb = (uint32_t)kk << 5;
            uint32_t a0[4], a1[4], bb[2];
            const uint32_t aaddr = a_row + wofs + ((kb + acl) ^ rxor);
            ldsm_x4(a0, aaddr);
            ldsm_x4(a1, aaddr + 16 * 256);
            ldsm_x2(bb, b_row + ((kb + bcl) ^ rxor));
            mma_f16(d[0], a0, bb[0], bb[1]);
            mma_f16(d[1], a1, bb[0], bb[1]);
        }
        #pragma unroll
        for (int mi = 0; mi < 2; mi++)
            #pragma unroll
            for (int k = 0; k < 4; k++) {
                const float v = d[mi][k] + bias[g][mi][k >> 1];
                if (g == 0)      G[mi][k] = ftanh(v);
                else if (g == 1) E[mi][k] = fsig(v) * G[mi][k];
                else             F[mi][k] = fsig(v);
            }
    }

    // ---- in-register affine scan ----
    float A[2][2], Bv[2][2];                    // [mi][hi]
    #pragma unroll
    for (int mi = 0; mi < 2; mi++)
        #pragma unroll
        for (int hi = 0; hi < 2; hi++) {
            const float e0 = E[mi][2 * hi], e1 = E[mi][2 * hi + 1];
            const float f0 = F[mi][2 * hi], f1 = F[mi][2 * hi + 1];
            A[mi][hi]  = f1 * f0;
            Bv[mi][hi] = f1 * e0 + e1;
        }
    #pragma unroll
    for (int delta = 1; delta <= 2; delta <<= 1) {
        #pragma unroll
        for (int mi = 0; mi < 2; mi++)
            #pragma unroll
            for (int hi = 0; hi < 2; hi++) {
                const float pA = __shfl_up_sync(0xffffffffu, A[mi][hi],  delta, 4);
                const float pB = __shfl_up_sync(0xffffffffu, Bv[mi][hi], delta, 4);
                if (j >= delta) {
                    Bv[mi][hi] = A[mi][hi] * pB + Bv[mi][hi];
                    A[mi][hi]  = A[mi][hi] * pA;
                }
            }
    }

    __syncthreads();                            // x tile dead -> reuse as seg
    float2* seg = (float2*)(smem + SM_X);       // [HDIM][4 n-warps]
    if (j == 3) {
        #pragma unroll
        for (int mi = 0; mi < 2; mi++)
            #pragma unroll
            for (int hi = 0; hi < 2; hi++) {
                const int h = m0 + 16 * mi + 8 * hi + r;
                seg[h * 4 + wn] = make_float2(A[mi][hi], Bv[mi][hi]);
            }
    }
    __syncthreads();

    if (tid < HDIM) {
        const int h = tid;
        const float2 s0 = seg[h * 4 + 0];
        float At = s0.x, Bt = s0.y;
        #pragma unroll
        for (int s = 1; s < 4; s++) {
            const float2 ss = seg[h * 4 + s];
            Bt = ss.x * Bt + ss.y;
            At = ss.x * At;
        }
        g_AB[(b * CHUNKS + ch) * HDIM + h] = make_float2(At, Bt);
    }
}

// ---------------------------------------------------------------------------
// final_kernel: o-gate at t = T-1 (fp32 dot), compose 64 chunk affines,
// classifier head. grid = BATCH, block = HDIM.
// ---------------------------------------------------------------------------
__global__ void final_kernel(const float* __restrict__ x,
                             const float* __restrict__ wo, const float* __restrict__ bo,
                             const float* __restrict__ fc1w, const float* __restrict__ fc1b,
                             const float* __restrict__ fc2w, const float* __restrict__ fc2b,
                             float* __restrict__ out)
{
    __shared__ float4 xrow[IDIM / 4];
    __shared__ float  hs[HDIM];
    __shared__ float  zs[FCDIM];
    __shared__ float  z2[ODIM];

    const int b = blockIdx.x;
    const int h = threadIdx.x;

    if (h < IDIM / 4)
        xrow[h] = ((const float4*)(x + (size_t)(T_LEN - 1) * (BATCH * IDIM) + b * IDIM))[h];

    // compose 64 chunk affines in 4 front-batched groups of 16
    float c = 0.0f;
    #pragma unroll
    for (int grp = 0; grp < 4; grp++) {
        float2 AB[16];
        #pragma unroll
        for (int k = 0; k < 16; k++)
            AB[k] = g_AB[(b * CHUNKS + grp * 16 + k) * HDIM + h];
        #pragma unroll
        for (int k = 0; k < 16; k++) c = AB[k].x * c + AB[k].y;
    }
    __syncthreads();

    // o-gate pre-activation (recurrent term is zero)
    float opre = bo[b * HDIM + h];
    const float4* wr = (const float4*)(wo + ((size_t)b * HDIM + h) * IDIM);
    #pragma unroll 8
    for (int k = 0; k < IDIM / 4; k++) {
        const float4 w4 = wr[k], x4 = xrow[k];
        opre += w4.x * x4.x + w4.y * x4.y + w4.z * x4.z + w4.w * x4.w;
    }
    const float o = 1.0f / (1.0f + expf(-opre));

    hs[h] = o * tanhf(c);
    __syncthreads();

    if (h < FCDIM) {
        float z = fc1b[h];
        const float4* w4p = (const float4*)(fc1w + h * HDIM);
        #pragma unroll 8
        for (int k = 0; k < HDIM / 4; k++) {
            const float4 w4 = w4p[k];
            z += w4.x * hs[4 * k] + w4.y * hs[4 * k + 1]
               + w4.z * hs[4 * k + 2] + w4.w * hs[4 * k + 3];
        }
        zs[h] = tanhf(z);
    }
    __syncthreads();

    if (h < ODIM) {
        float z = fc2b[h];
        #pragma unroll
        for (int k = 0; k < FCDIM; k++) z += fc2w[h * FCDIM + k] * zs[k];
        z2[h] = z;
    }
    __syncthreads();

    if (h == 0) {
        const float m   = fmaxf(z2[0], z2[1]);
        const float lse = m + logf(expf(z2[0] - m) + expf(z2[1] - m));
        out[b * ODIM + 0] = z2[0] - lse;
        out[b * ODIM + 1] = z2[1] - lse;
    }
}

// ---------------------------------------------------------------------------
extern "C" void kernel_launch(void* const* d_in, const int* in_sizes, int n_in,
                              void* d_out, int out_size)
{
    const float* x   = (const float*)d_in[0];
    const float* wg  = (const float*)d_in[1];
    const float* wi  = (const float*)d_in[2];
    const float* wf  = (const float*)d_in[3];
    const float* wo  = (const float*)d_in[4];
    // d_in[5..8] (recurrent weights) multiply a zero hidden state -> unused.
    const float* bg  = (const float*)d_in[9];
    const float* bi  = (const float*)d_in[10];
    const float* bf  = (const float*)d_in[11];
    const float* bo  = (const float*)d_in[12];
    const float* f1w = (const float*)d_in[13];
    const float* f1b = (const float*)d_in[14];
    const float* f2w = (const float*)d_in[15];
    const float* f2b = (const float*)d_in[16];

    cudaFuncSetAttribute(gates_kernel,
                         cudaFuncAttributeMaxDynamicSharedMemorySize, SM_TOTAL);

    prep_kernel<<<3 * BATCH, 256>>>(wg, wi, wf);
    gates_kernel<<<dim3(CHUNKS, BATCH), NTH, SM_TOTAL>>>(x, bg, bi, bf);
    final_kernel<<<BATCH, HDIM>>>(x, wo, bo, f1w, f1b, f2w, f2b, (float*)d_out);
}

// round 9
// speedup vs baseline: 16.8125x; 1.0412x over previous
#include <cuda_runtime.h>
#include <cuda_fp16.h>
#include <cstdint>

// ---------------- problem constants ----------------
#define T_LEN   2048
#define BATCH   64
#define IDIM    128
#define HDIM    128
#define FCDIM   32
#define ODIM    2
#define TCH     32                  // timesteps per chunk (MMA N)
#define CHUNKS  (T_LEN / TCH)       // 64
#define NTH     512

// ---------------- global scratch -------------------------------------------
__device__ __align__(16) __half g_wH[3 * BATCH * HDIM * IDIM];  // fp16 W (g,i,f)
__device__ float2 g_AB[BATCH * CHUNKS * HDIM];                  // chunk affine (A,B)

// ---------------- SMEM layout (bytes) --------------------------------------
// x tile 32 x 256B = 8192; W tiles 3 x 128 x 256B = 98304. seg reuses x region.
#define SM_X     0
#define SM_W     8192
#define SM_TOTAL 106496

// ---------------- helpers ---------------------------------------------------
__device__ __forceinline__ uint32_t smem_u32(const void* p) {
    uint32_t a;
    asm("{ .reg .u64 t; cvta.to.shared.u64 t, %1; cvt.u32.u64 %0, t; }"
        : "=r"(a) : "l"(p));
    return a;
}
__device__ __forceinline__ void cp_async16(uint32_t dst, const void* src) {
    asm volatile("cp.async.cg.shared.global [%0], [%1], 16;"
                 :: "r"(dst), "l"(src) : "memory");
}
__device__ __forceinline__ void cp_commit_wait() {
    asm volatile("cp.async.commit_group;" ::: "memory");
    asm volatile("cp.async.wait_group 0;" ::: "memory");
}
__device__ __forceinline__ void ldsm_x4(uint32_t (&r)[4], uint32_t addr) {
    asm volatile("ldmatrix.sync.aligned.m8n8.x4.shared.b16 {%0,%1,%2,%3}, [%4];"
                 : "=r"(r[0]), "=r"(r[1]), "=r"(r[2]), "=r"(r[3]) : "r"(addr));
}
__device__ __forceinline__ void ldsm_x2(uint32_t (&r)[2], uint32_t addr) {
    asm volatile("ldmatrix.sync.aligned.m8n8.x2.shared.b16 {%0,%1}, [%2];"
                 : "=r"(r[0]), "=r"(r[1]) : "r"(addr));
}
__device__ __forceinline__ void mma_f16(float (&d)[4], const uint32_t (&a)[4],
                                        uint32_t b0, uint32_t b1) {
    asm volatile("mma.sync.aligned.m16n8k16.row.col.f32.f16.f16.f32 "
                 "{%0,%1,%2,%3}, {%4,%5,%6,%7}, {%8,%9}, {%0,%1,%2,%3};"
                 : "+f"(d[0]), "+f"(d[1]), "+f"(d[2]), "+f"(d[3])
                 : "r"(a[0]), "r"(a[1]), "r"(a[2]), "r"(a[3]), "r"(b0), "r"(b1));
}
// pack 8 fp32 -> 8 fp16
__device__ __forceinline__ uint4 cvt8h(float4 a, float4 b) {
    uint4 r;
    r.x = __half_as_ushort(__float2half_rn(a.x)) |
          ((uint32_t)__half_as_ushort(__float2half_rn(a.y)) << 16);
    r.y = __half_as_ushort(__float2half_rn(a.z)) |
          ((uint32_t)__half_as_ushort(__float2half_rn(a.w)) << 16);
    r.z = __half_as_ushort(__float2half_rn(b.x)) |
          ((uint32_t)__half_as_ushort(__float2half_rn(b.y)) << 16);
    r.w = __half_as_ushort(__float2half_rn(b.z)) |
          ((uint32_t)__half_as_ushort(__float2half_rn(b.w)) << 16);
    return r;
}
__device__ __forceinline__ float fsig(float x)  { return 1.0f / (1.0f + __expf(-x)); }
__device__ __forceinline__ float ftanh(float x) { return 2.0f * fsig(2.0f * x) - 1.0f; }

// ---------------------------------------------------------------------------
// prep_kernel: W (g,i,f) fp32 -> fp16 global, layout [g][b][h][i].
// grid = 768 (plane*4 + quarter), block = 256 -> 5.3 waves, latency-hidden.
// ---------------------------------------------------------------------------
__global__ void prep_kernel(const float* __restrict__ wg,
                            const float* __restrict__ wi,
                            const float* __restrict__ wf)
{
    const int plane = blockIdx.x >> 2;          // g*64 + b
    const int quarter = blockIdx.x & 3;
    const int g = plane >> 6, b = plane & 63;
    const float* src = ((g == 0) ? wg : (g == 1) ? wi : wf) + (size_t)b * HDIM * IDIM;
    __half* dst = g_wH + (size_t)plane * HDIM * IDIM;
    const int base = quarter * 512;             // 512 of 2048 8-elt units
    #pragma unroll
    for (int it = 0; it < 2; it++) {
        const int u = base + it * 256 + threadIdx.x;
        const float4* p = (const float4*)(src + u * 8);
        *(uint4*)(dst + u * 8) = cvt8h(p[0], p[1]);
    }
}

// ---------------------------------------------------------------------------
// gates_kernel: grid (CHUNKS, BATCH) = (64, 64); block 512, occ 2.
// preact[h,t] = sum_i W[b,h,i] x[t0+t,b,i] for gates {g,i,f} via fp16
// mma.sync; W via cp.async (prepped fp16), XOR-swizzled 256B-row tiles;
// activations + chunk affine scan in registers (pair -> quad shfl -> 4 segs).
// UNCHANGED from round 8 (pipe-saturated at legacy-mma roofline).
// ---------------------------------------------------------------------------
__global__ void __launch_bounds__(NTH, 2)
gates_kernel(const float* __restrict__ x,
             const float* __restrict__ bg, const float* __restrict__ bi,
             const float* __restrict__ bf_)
{
    extern __shared__ char smem[];
    const uint32_t sb = smem_u32(smem);
    const int tid  = threadIdx.x;
    const int wid  = tid >> 5;
    const int lane = tid & 31;
    const int b  = blockIdx.y;
    const int ch = blockIdx.x;
    const int t0 = ch * TCH;

    // ---- cp.async all 3 gate W tiles (fp16, swizzled 256B rows) ----
    #pragma unroll
    for (int it = 0; it < 12; it++) {                 // 6144 16B units
        const int u = tid + it * NTH;
        const int g = u >> 11, rem = u & 2047;
        const int row = rem >> 4, cb = (rem & 15) << 4;       // col bytes
        const __half* src = g_wH + ((size_t)(g * BATCH + b) * (HDIM * IDIM))
                                 + row * IDIM + (cb >> 1);
        cp_async16(sb + SM_W + g * 32768 + row * 256 + (cb ^ ((row & 7) << 4)), src);
    }
    // ---- x chunk: 512 16B units -> fp16 swizzled (overlaps cp.async) ----
    {
        const int row = tid >> 4, cb = (tid & 15) << 4;       // col bytes (fp16)
        const float4* p = (const float4*)(x + (size_t)(t0 + row) * (BATCH * IDIM)
                                            + (size_t)b * IDIM + (cb >> 1));
        *(uint4*)(smem + SM_X + row * 256 + (cb ^ ((row & 7) << 4))) = cvt8h(p[0], p[1]);
    }
    cp_commit_wait();
    __syncthreads();

    // ---- warp tiling: 4m x 4n; warp tile m32 x n8 ----
    const int wm = wid >> 2, wn = wid & 3;
    const int m0 = wm * 32, n0 = wn * 8;
    const int j  = lane & 3;                    // t-pair index
    const int r  = lane >> 2;                   // row-within-8

    const uint32_t rxor  = (uint32_t)((lane & 7) << 4);
    const uint32_t a_row = sb + SM_W + (uint32_t)(m0 + (lane & 15)) * 256;
    const uint32_t acl   = (uint32_t)((lane >> 4) << 4);
    const uint32_t b_row = sb + SM_X + (uint32_t)(n0 + (lane & 7)) * 256;
    const uint32_t bcl   = (uint32_t)(((lane >> 3) & 1) << 4);

    float bias[3][2][2];
    #pragma unroll
    for (int mi = 0; mi < 2; mi++)
        #pragma unroll
        for (int hi = 0; hi < 2; hi++) {
            const int h = m0 + 16 * mi + 8 * hi + r;
            bias[0][mi][hi] = bg[b * HDIM + h];
            bias[1][mi][hi] = bi[b * HDIM + h];
            bias[2][mi][hi] = bf_[b * HDIM + h];
        }

    float G[2][4], E[2][4], F[2][4];
    #pragma unroll
    for (int g = 0; g < 3; g++) {
        float d[2][4];
        #pragma unroll
        for (int mi = 0; mi < 2; mi++)
            #pragma unroll
            for (int k = 0; k < 4; k++) d[mi][k] = 0.0f;
        const uint32_t wofs = (uint32_t)g * 32768u;
        #pragma unroll
        for (int kk = 0; kk < 8; kk++) {
            const uint32_t kb = (uint32_t)kk << 5;
            uint32_t a0[4], a1[4], bb[2];
            const uint32_t aaddr = a_row + wofs + ((kb + acl) ^ rxor);
            ldsm_x4(a0, aaddr);
            ldsm_x4(a1, aaddr + 16 * 256);
            ldsm_x2(bb, b_row + ((kb + bcl) ^ rxor));
            mma_f16(d[0], a0, bb[0], bb[1]);
            mma_f16(d[1], a1, bb[0], bb[1]);
        }
        #pragma unroll
        for (int mi = 0; mi < 2; mi++)
            #pragma unroll
            for (int k = 0; k < 4; k++) {
                const float v = d[mi][k] + bias[g][mi][k >> 1];
                if (g == 0)      G[mi][k] = ftanh(v);
                else if (g == 1) E[mi][k] = fsig(v) * G[mi][k];
                else             F[mi][k] = fsig(v);
            }
    }

    // ---- in-register affine scan ----
    float A[2][2], Bv[2][2];                    // [mi][hi]
    #pragma unroll
    for (int mi = 0; mi < 2; mi++)
        #pragma unroll
        for (int hi = 0; hi < 2; hi++) {
            const float e0 = E[mi][2 * hi], e1 = E[mi][2 * hi + 1];
            const float f0 = F[mi][2 * hi], f1 = F[mi][2 * hi + 1];
            A[mi][hi]  = f1 * f0;
            Bv[mi][hi] = f1 * e0 + e1;
        }
    #pragma unroll
    for (int delta = 1; delta <= 2; delta <<= 1) {
        #pragma unroll
        for (int mi = 0; mi < 2; mi++)
            #pragma unroll
            for (int hi = 0; hi < 2; hi++) {
                const float pA = __shfl_up_sync(0xffffffffu, A[mi][hi],  delta, 4);
                const float pB = __shfl_up_sync(0xffffffffu, Bv[mi][hi], delta, 4);
                if (j >= delta) {
                    Bv[mi][hi] = A[mi][hi] * pB + Bv[mi][hi];
                    A[mi][hi]  = A[mi][hi] * pA;
                }
            }
    }

    __syncthreads();                            // x tile dead -> reuse as seg
    float2* seg = (float2*)(smem + SM_X);       // [HDIM][4 n-warps]
    if (j == 3) {
        #pragma unroll
        for (int mi = 0; mi < 2; mi++)
            #pragma unroll
            for (int hi = 0; hi < 2; hi++) {
                const int h = m0 + 16 * mi + 8 * hi + r;
                seg[h * 4 + wn] = make_float2(A[mi][hi], Bv[mi][hi]);
            }
    }
    __syncthreads();

    if (tid < HDIM) {
        const int h = tid;
        const float2 s0 = seg[h * 4 + 0];
        float At = s0.x, Bt = s0.y;
        #pragma unroll
        for (int s = 1; s < 4; s++) {
            const float2 ss = seg[h * 4 + s];
            Bt = ss.x * Bt + ss.y;
            At = ss.x * At;
        }
        g_AB[(b * CHUNKS + ch) * HDIM + h] = make_float2(At, Bt);
    }
}

// ---------------------------------------------------------------------------
// final_kernel: grid = BATCH, block = 512. thread = (seg, h) with seg = tid>>7.
// All 4 segs compose 16 chunk-affines in parallel; seg-1 threads concurrently
// do the o-gate dot (t = T-1); combine via smem; classifier head on seg 0.
// ---------------------------------------------------------------------------
__global__ void __launch_bounds__(512)
final_kernel(const float* __restrict__ x,
             const float* __restrict__ wo, const float* __restrict__ bo,
             const float* __restrict__ fc1w, const float* __restrict__ fc1b,
             const float* __restrict__ fc2w, const float* __restrict__ fc2b,
             float* __restrict__ out)
{
    __shared__ float4 xrow[IDIM / 4];
    __shared__ float2 segs[4 * HDIM];
    __shared__ float  opre_s[HDIM];
    __shared__ float  hs[HDIM];
    __shared__ float  zs[FCDIM];
    __shared__ float  z2[ODIM];

    const int b   = blockIdx.x;
    const int tid = threadIdx.x;
    const int h   = tid & 127;
    const int sg  = tid >> 7;

    if (tid < IDIM / 4)
        xrow[tid] = ((const float4*)(x + (size_t)(T_LEN - 1) * (BATCH * IDIM) + b * IDIM))[tid];

    // every thread: front-batched load of its 16 chunk affines
    float2 AB[16];
    #pragma unroll
    for (int k = 0; k < 16; k++)
        AB[k] = g_AB[(b * CHUNKS + sg * 16 + k) * HDIM + h];
    __syncthreads();                    // xrow visible

    // seg-1 threads: o-gate pre-activation dot (concurrent with composes)
    if (sg == 1) {
        float opre = bo[b * HDIM + h];
        const float4* wr = (const float4*)(wo + ((size_t)b * HDIM + h) * IDIM);
        #pragma unroll 8
        for (int k = 0; k < IDIM / 4; k++) {
            const float4 w4 = wr[k], x4 = xrow[k];
            opre += w4.x * x4.x + w4.y * x4.y + w4.z * x4.z + w4.w * x4.w;
        }
        opre_s[h] = opre;
    }

    // all threads: compose own 16 chunks (ascending)
    float At = AB[0].x, Bt = AB[0].y;
    #pragma unroll
    for (int k = 1; k < 16; k++) {
        Bt = AB[k].x * Bt + AB[k].y;
        At = AB[k].x * At;
    }
    segs[sg * HDIM + h] = make_float2(At, Bt);
    __syncthreads();

    if (sg == 0) {
        float c = Bt;                    // own seg (s=0) already composed
        #pragma unroll
        for (int s = 1; s < 4; s++) {
            const float2 ss = segs[s * HDIM + h];
            c = ss.x * c + ss.y;
        }
        const float o = 1.0f / (1.0f + expf(-opre_s[h]));
        hs[h] = o * tanhf(c);
    }
    __syncthreads();

    if (tid < FCDIM) {
        float z = fc1b[tid];
        const float4* w4p = (const float4*)(fc1w + tid * HDIM);
        #pragma unroll 8
        for (int k = 0; k < HDIM / 4; k++) {
            const float4 w4 = w4p[k];
            z += w4.x * hs[4 * k] + w4.y * hs[4 * k + 1]
               + w4.z * hs[4 * k + 2] + w4.w * hs[4 * k + 3];
        }
        zs[tid] = tanhf(z);
    }
    __syncthreads();

    if (tid < ODIM) {
        float z = fc2b[tid];
        #pragma unroll
        for (int k = 0; k < FCDIM; k++) z += fc2w[tid * FCDIM + k] * zs[k];
        z2[tid] = z;
    }
    __syncthreads();

    if (tid == 0) {
        const float m   = fmaxf(z2[0], z2[1]);
        const float lse = m + logf(expf(z2[0] - m) + expf(z2[1] - m));
        out[b * ODIM + 0] = z2[0] - lse;
        out[b * ODIM + 1] = z2[1] - lse;
    }
}

// ---------------------------------------------------------------------------
extern "C" void kernel_launch(void* const* d_in, const int* in_sizes, int n_in,
                              void* d_out, int out_size)
{
    const float* x   = (const float*)d_in[0];
    const float* wg  = (const float*)d_in[1];
    const float* wi  = (const float*)d_in[2];
    const float* wf  = (const float*)d_in[3];
    const float* wo  = (const float*)d_in[4];
    // d_in[5..8] (recurrent weights) multiply a zero hidden state -> unused.
    const float* bg  = (const float*)d_in[9];
    const float* bi  = (const float*)d_in[10];
    const float* bf  = (const float*)d_in[11];
    const float* bo  = (const float*)d_in[12];
    const float* f1w = (const float*)d_in[13];
    const float* f1b = (const float*)d_in[14];
    const float* f2w = (const float*)d_in[15];
    const float* f2b = (const float*)d_in[16];

    cudaFuncSetAttribute(gates_kernel,
                         cudaFuncAttributeMaxDynamicSharedMemorySize, SM_TOTAL);

    prep_kernel<<<3 * BATCH * 4, 256>>>(wg, wi, wf);
    gates_kernel<<<dim3(CHUNKS, BATCH), NTH, SM_TOTAL>>>(x, bg, bi, bf);
    final_kernel<<<BATCH, 512>>>(x, wo, bo, f1w, f1b, f2w, f2b, (float*)d_out);
}